// round 5
// baseline (speedup 1.0000x reference)
#include <cuda_runtime.h>
#include <math.h>
#include <stdint.h>

#define NB     4
#define CH     512
#define LSEQ   2048
#define NHEADS 8
#define DHEAD  64
#define QKV_CH 1536

// ---------------------------------------------------------------------------
// Scratch (no cudaMalloc allowed)
// ---------------------------------------------------------------------------
__device__ float g_qkv[(size_t)NB * QKV_CH * LSEQ];   // ~50 MB  (tf32-rounded)
__device__ float g_att[(size_t)NB * CH * LSEQ];       // ~17 MB  (tf32-rounded)
__device__ float g_x[(size_t)NB * CH * LSEQ];         // ~17 MB  (tf32-rounded x)
__device__ float g_wqkvT[CH * QKV_CH];                // w_qkv^T, rounded
__device__ float g_woutT[CH * CH];                    // w_out^T, rounded

// ---------------------------------------------------------------------------
// helpers
// ---------------------------------------------------------------------------
__device__ __forceinline__ float tf32r(float x) {
    uint32_t u;
    asm("cvt.rna.tf32.f32 %0, %1;" : "=r"(u) : "f"(x));
    return __uint_as_float(u);
}
__device__ __forceinline__ uint32_t fau(float x) { return __float_as_uint(x); }

__device__ __forceinline__ float ex2(float x) {
    float r;
    asm("ex2.approx.f32 %0, %1;" : "=f"(r) : "f"(x));
    return r;
}

__device__ __forceinline__ void mma_tf32(float c[4],
    uint32_t a0, uint32_t a1, uint32_t a2, uint32_t a3,
    uint32_t b0, uint32_t b1)
{
    asm volatile(
        "mma.sync.aligned.m16n8k8.row.col.f32.tf32.tf32.f32 "
        "{%0,%1,%2,%3}, {%4,%5,%6,%7}, {%8,%9}, {%0,%1,%2,%3};"
        : "+f"(c[0]), "+f"(c[1]), "+f"(c[2]), "+f"(c[3])
        : "r"(a0), "r"(a1), "r"(a2), "r"(a3), "r"(b0), "r"(b1));
}

__device__ __forceinline__ void cp128(uint32_t dst, const void* src) {
    asm volatile("cp.async.cg.shared.global [%0], [%1], 16;" :: "r"(dst), "l"(src));
}
#define CP_COMMIT() asm volatile("cp.async.commit_group;")
#define CP_WAIT(N)  asm volatile("cp.async.wait_group %0;" :: "n"(N))

// ---------------------------------------------------------------------------
// prep kernels
// ---------------------------------------------------------------------------
__global__ void round4_kernel(const float4* __restrict__ in, float4* __restrict__ out, int n4)
{
    int i = blockIdx.x * blockDim.x + threadIdx.x;
    if (i < n4) {
        float4 v = in[i];
        out[i] = make_float4(tf32r(v.x), tf32r(v.y), tf32r(v.z), tf32r(v.w));
    }
}

__global__ void transpose_round(const float* __restrict__ in, float* __restrict__ out,
                                int M, int K)
{
    __shared__ float tile[32][33];
    const int k0 = blockIdx.x * 32;
    const int m0 = blockIdx.y * 32;
    const int tx = threadIdx.x, ty = threadIdx.y;
#pragma unroll
    for (int r = 0; r < 32; r += 8)
        tile[ty + r][tx] = tf32r(in[(size_t)(m0 + ty + r) * K + k0 + tx]);
    __syncthreads();
#pragma unroll
    for (int r = 0; r < 32; r += 8)
        out[(size_t)(k0 + ty + r) * M + m0 + tx] = tile[tx][ty + r];
}

// ---------------------------------------------------------------------------
// GEMM v2: 128x128 block, 4 warps (2x2), warp tile 64x64, k-step 16,
// 3-stage cp.async. Every fragment feeds 4-8 MMAs: 32 LDS : 32 HMMA per k8.
// ---------------------------------------------------------------------------
#define GP     136
#define GSTG   (16 * GP)
#define G_SMEM (2 * 3 * GSTG * (int)sizeof(float))

__global__ __launch_bounds__(128, 2)
void gemm_cp(const float* __restrict__ AT, const float* __restrict__ B,
             float* __restrict__ C, const float* __restrict__ bias,
             int M, int N, int K, long strideB, long strideC, int round_out)
{
    extern __shared__ float gsm[];
    float* Asm = gsm;
    float* Bsm = gsm + 3 * GSTG;

    const int t    = threadIdx.x;
    const int lane = t & 31;
    const int w    = t >> 5;      // 0..3
    const int qr   = lane >> 2;
    const int qc   = lane & 3;
    const int bm   = blockIdx.y * 128;
    const int bn   = blockIdx.x * 128;

    B += (long)blockIdx.z * strideB;
    C += (long)blockIdx.z * strideC;

    const int wm = (w >> 1) * 64;
    const int wn = (w & 1) * 64;

    const uint32_t aBase = (uint32_t)__cvta_generic_to_shared(Asm);
    const uint32_t bBase = (uint32_t)__cvta_generic_to_shared(Bsm);

    const int srow  = t >> 3;        // 0..15
    const int sblk  = t & 7;         // float4 lane 0..7 (of 32)
    const int nslabs = K / 16;

    auto stage = [&](int slab, int buf) {
        const float* aSrc = AT + (size_t)(slab * 16 + srow) * M + bm;
        const float* bSrc = B  + (size_t)(slab * 16 + srow) * N + bn;
        uint32_t aDst = aBase + (uint32_t)((buf * GSTG + srow * GP) * 4);
        uint32_t bDst = bBase + (uint32_t)((buf * GSTG + srow * GP) * 4);
#pragma unroll
        for (int c = 0; c < 4; c++) {
            const int col = (sblk + 8 * c) * 4;
            cp128(aDst + col * 4, aSrc + col);
            cp128(bDst + col * 4, bSrc + col);
        }
    };

    float acc[4][8][4];
#pragma unroll
    for (int i = 0; i < 4; i++)
#pragma unroll
        for (int j = 0; j < 8; j++)
#pragma unroll
            for (int r = 0; r < 4; r++) acc[i][j][r] = 0.0f;

    stage(0, 0); CP_COMMIT();
    stage(1, 1); CP_COMMIT();

    for (int i = 0; i < nslabs; i++) {
        const int s = i % 3;
        if (i + 2 < nslabs) { stage(i + 2, (i + 2) % 3); CP_COMMIT(); CP_WAIT(2); }
        else if (i + 1 < nslabs) { CP_WAIT(1); }
        else { CP_WAIT(0); }
        __syncthreads();

        const float* As = Asm + s * GSTG;
        const float* Bs = Bsm + s * GSTG;

#pragma unroll
        for (int ks = 0; ks < 16; ks += 8) {
            uint32_t af[4][4];
#pragma unroll
            for (int mf = 0; mf < 4; mf++) {
                const int mi = wm + mf * 16 + qr;
                af[mf][0] = fau(As[(ks + qc)     * GP + mi]);
                af[mf][1] = fau(As[(ks + qc)     * GP + mi + 8]);
                af[mf][2] = fau(As[(ks + qc + 4) * GP + mi]);
                af[mf][3] = fau(As[(ks + qc + 4) * GP + mi + 8]);
            }
            uint32_t bf[8][2];
#pragma unroll
            for (int nf = 0; nf < 8; nf++) {
                const int ni = wn + nf * 8 + qr;
                bf[nf][0] = fau(Bs[(ks + qc)     * GP + ni]);
                bf[nf][1] = fau(Bs[(ks + qc + 4) * GP + ni]);
            }
#pragma unroll
            for (int nf = 0; nf < 8; nf++)
#pragma unroll
                for (int mf = 0; mf < 4; mf++)
                    mma_tf32(acc[mf][nf], af[mf][0], af[mf][1], af[mf][2], af[mf][3],
                             bf[nf][0], bf[nf][1]);
        }
        __syncthreads();
    }

#pragma unroll
    for (int mf = 0; mf < 4; mf++) {
        const int row = bm + wm + mf * 16 + qr;
        const float bv0 = bias ? bias[row]     : 0.0f;
        const float bv1 = bias ? bias[row + 8] : 0.0f;
#pragma unroll
        for (int nf = 0; nf < 8; nf++) {
            const int col = bn + wn + nf * 8 + qc * 2;
            float o00 = acc[mf][nf][0] + bv0, o01 = acc[mf][nf][1] + bv0;
            float o10 = acc[mf][nf][2] + bv1, o11 = acc[mf][nf][3] + bv1;
            if (round_out) {
                o00 = tf32r(o00); o01 = tf32r(o01);
                o10 = tf32r(o10); o11 = tf32r(o11);
            }
            *(float2*)(C + (size_t)row * N + col)       = make_float2(o00, o01);
            *(float2*)(C + (size_t)(row + 8) * N + col) = make_float2(o10, o11);
        }
    }
}

// ---------------------------------------------------------------------------
// Flash attention v5: Bq=256, 256 threads, 8 warps x m32n64.
// Base-2 softmax (log2e folded into Q scale, single MUFU per exp),
// conditional O-rescale. Q fragment-major; K/V double-buffered cp.async;
// P stays in registers via shfl permutation.
// ---------------------------------------------------------------------------
#define QSCALE    (0.125f * 1.4426950408889634f)
#define KP        72
#define VP        68
#define QF_WORDS  (8 * 16 * 32 * 4)
#define KS_WORDS  (64 * KP)
#define VS_WORDS  (64 * VP)
#define FL_SMEM   ((QF_WORDS + 2 * KS_WORDS + 2 * VS_WORDS) * (int)sizeof(float))

__global__ __launch_bounds__(256, 1)
void flash5(const float* __restrict__ qkv, float* __restrict__ out)
{
    extern __shared__ float sm[];
    float* Qf  = sm;
    float* KsA = sm + QF_WORDS;
    float* VsA = KsA + 2 * KS_WORDS;

    const int t    = threadIdx.x;
    const int lane = t & 31;
    const int w    = t >> 5;
    const int qr   = lane >> 2;
    const int qc   = lane & 3;
    const int i0   = blockIdx.x * 256;
    const int nh   = blockIdx.y;
    const int n    = nh >> 3, h = nh & 7;

    const float* qb = qkv + ((size_t)n * QKV_CH + h * DHEAD) * LSEQ;
    const float* kb = qb + (size_t)CH * LSEQ;
    const float* vb = qb + 2 * (size_t)CH * LSEQ;

    const uint32_t ksBase = (uint32_t)__cvta_generic_to_shared(KsA);
    const uint32_t vsBase = (uint32_t)__cvta_generic_to_shared(VsA);

    const int sd = t >> 2;
    const int sc = t & 3;

    auto stageKV = [&](int jt, int buf) {
        const float* ksrc = kb + (size_t)sd * LSEQ + jt * 64;
        const float* vsrc = vb + (size_t)sd * LSEQ + jt * 64;
        uint32_t kdst = ksBase + (uint32_t)((buf * KS_WORDS + sd * KP) * 4);
        uint32_t vdst = vsBase + (uint32_t)((buf * VS_WORDS + sd * VP) * 4);
#pragma unroll
        for (int c = 0; c < 4; c++) {
            const int j4 = (sc + 4 * c) * 4;
            cp128(kdst + j4 * 4, ksrc + j4);
            cp128(vdst + j4 * 4, vsrc + j4);
        }
    };

    stageKV(0, 0); CP_COMMIT();

    // stage Q once, fragment-major, scaled by 2^-3*log2e then tf32-rounded
    {
        const int d  = t >> 2;
        const int ic = (t & 3) * 64;
        const int kk = d >> 3, kc = d & 7;
        const int rbase = (kc >= 4) ? 2 : 0;
#pragma unroll
        for (int m = 0; m < 16; m++) {
            float4 v = *(const float4*)(qb + (size_t)d * LSEQ + i0 + ic + m * 4);
            float vv[4] = {v.x, v.y, v.z, v.w};
#pragma unroll
            for (int e = 0; e < 4; e++) {
                const int il = ic + m * 4 + e;
                const int wq = il >> 4, rr = il & 7, hi = (il >> 3) & 1;
                Qf[((kk * 16 + wq) * 32 + rr * 4 + (kc & 3)) * 4 + rbase + hi]
                    = tf32r(vv[e] * QSCALE);
            }
        }
    }

    float mrow[2][2], lrow[2][2];
    float o[2][8][4];
#pragma unroll
    for (int mf = 0; mf < 2; mf++) {
        mrow[mf][0] = -1e30f; mrow[mf][1] = -1e30f;
        lrow[mf][0] = 0.0f;   lrow[mf][1] = 0.0f;
#pragma unroll
        for (int df = 0; df < 8; df++)
#pragma unroll
            for (int r = 0; r < 4; r++) o[mf][df][r] = 0.0f;
    }

    const int njt = LSEQ / 64;
    for (int jt = 0; jt < njt; jt++) {
        const int s = jt & 1;
        if (jt + 1 < njt) { stageKV(jt + 1, s ^ 1); CP_COMMIT(); CP_WAIT(1); }
        else { CP_WAIT(0); }
        __syncthreads();

        const float* Kb = KsA + s * KS_WORDS;
        const float* Vb = VsA + s * VS_WORDS;

        // ---- S = Q^T K (logits already in base-2 domain) ----
        float sreg[2][8][4];
#pragma unroll
        for (int mf = 0; mf < 2; mf++)
#pragma unroll
            for (int nf = 0; nf < 8; nf++)
#pragma unroll
                for (int r = 0; r < 4; r++) sreg[mf][nf][r] = 0.0f;

#pragma unroll
        for (int kk = 0; kk < 8; kk++) {
            float4 aA = *(const float4*)&Qf[((kk * 16 + w * 2 + 0) * 32 + lane) * 4];
            float4 aB = *(const float4*)&Qf[((kk * 16 + w * 2 + 1) * 32 + lane) * 4];
            uint32_t a00 = fau(aA.x), a01 = fau(aA.y), a02 = fau(aA.z), a03 = fau(aA.w);
            uint32_t a10 = fau(aB.x), a11 = fau(aB.y), a12 = fau(aB.z), a13 = fau(aB.w);
#pragma unroll
            for (int nf = 0; nf < 8; nf++) {
                uint32_t b0 = fau(Kb[(kk * 8 + qc)     * KP + nf * 8 + qr]);
                uint32_t b1 = fau(Kb[(kk * 8 + qc + 4) * KP + nf * 8 + qr]);
                mma_tf32(sreg[0][nf], a00, a01, a02, a03, b0, b1);
                mma_tf32(sreg[1][nf], a10, a11, a12, a13, b0, b1);
            }
        }

        // ---- online softmax (base 2) ----
#pragma unroll
        for (int mf = 0; mf < 2; mf++) {
            float rm0 = -1e30f, rm1 = -1e30f;
#pragma unroll
            for (int nf = 0; nf < 8; nf++) {
                rm0 = fmaxf(rm0, fmaxf(sreg[mf][nf][0], sreg[mf][nf][1]));
                rm1 = fmaxf(rm1, fmaxf(sreg[mf][nf][2], sreg[mf][nf][3]));
            }
            rm0 = fmaxf(rm0, __shfl_xor_sync(0xffffffffu, rm0, 1));
            rm0 = fmaxf(rm0, __shfl_xor_sync(0xffffffffu, rm0, 2));
            rm1 = fmaxf(rm1, __shfl_xor_sync(0xffffffffu, rm1, 1));
            rm1 = fmaxf(rm1, __shfl_xor_sync(0xffffffffu, rm1, 2));

            const float mn0 = fmaxf(mrow[mf][0], rm0);
            const float mn1 = fmaxf(mrow[mf][1], rm1);
            const float al0 = ex2(mrow[mf][0] - mn0);
            const float al1 = ex2(mrow[mf][1] - mn1);
            mrow[mf][0] = mn0; mrow[mf][1] = mn1;

            float rs0 = 0.0f, rs1 = 0.0f;
#pragma unroll
            for (int nf = 0; nf < 8; nf++) {
                sreg[mf][nf][0] = ex2(sreg[mf][nf][0] - mn0);
                sreg[mf][nf][1] = ex2(sreg[mf][nf][1] - mn0);
                sreg[mf][nf][2] = ex2(sreg[mf][nf][2] - mn1);
                sreg[mf][nf][3] = ex2(sreg[mf][nf][3] - mn1);
                rs0 += sreg[mf][nf][0] + sreg[mf][nf][1];
                rs1 += sreg[mf][nf][2] + sreg[mf][nf][3];
            }
            rs0 += __shfl_xor_sync(0xffffffffu, rs0, 1);
            rs0 += __shfl_xor_sync(0xffffffffu, rs0, 2);
            rs1 += __shfl_xor_sync(0xffffffffu, rs1, 1);
            rs1 += __shfl_xor_sync(0xffffffffu, rs1, 2);

            lrow[mf][0] = lrow[mf][0] * al0 + rs0;
            lrow[mf][1] = lrow[mf][1] * al1 + rs1;

            if (!__all_sync(0xffffffffu, (al0 == 1.0f) && (al1 == 1.0f))) {
#pragma unroll
                for (int df = 0; df < 8; df++) {
                    o[mf][df][0] *= al0; o[mf][df][1] *= al0;
                    o[mf][df][2] *= al1; o[mf][df][3] *= al1;
                }
            }
            // round P to tf32 in registers
#pragma unroll
            for (int nf = 0; nf < 8; nf++)
#pragma unroll
                for (int r = 0; r < 4; r++) sreg[mf][nf][r] = tf32r(sreg[mf][nf][r]);
        }

        // ---- O += P @ V^T ----
        const int lsrc0 = (lane & ~3) | (qc >> 1);
        const int lsrc2 = lsrc0 + 2;
        const bool odd  = qc & 1;
#pragma unroll
        for (int kb2 = 0; kb2 < 8; kb2++) {
            uint32_t af[2][4];
#pragma unroll
            for (int mf = 0; mf < 2; mf++) {
                float v00 = __shfl_sync(0xffffffffu, sreg[mf][kb2][0], lsrc0);
                float v01 = __shfl_sync(0xffffffffu, sreg[mf][kb2][1], lsrc0);
                float v10 = __shfl_sync(0xffffffffu, sreg[mf][kb2][2], lsrc0);
                float v11 = __shfl_sync(0xffffffffu, sreg[mf][kb2][3], lsrc0);
                float w00 = __shfl_sync(0xffffffffu, sreg[mf][kb2][0], lsrc2);
                float w01 = __shfl_sync(0xffffffffu, sreg[mf][kb2][1], lsrc2);
                float w10 = __shfl_sync(0xffffffffu, sreg[mf][kb2][2], lsrc2);
                float w11 = __shfl_sync(0xffffffffu, sreg[mf][kb2][3], lsrc2);
                af[mf][0] = fau(odd ? v01 : v00);
                af[mf][1] = fau(odd ? v11 : v10);
                af[mf][2] = fau(odd ? w01 : w00);
                af[mf][3] = fau(odd ? w11 : w10);
            }
#pragma unroll
            for (int df = 0; df < 8; df++) {
                uint32_t b0 = fau(Vb[(df * 8 + qr) * VP + kb2 * 8 + qc]);
                uint32_t b1 = fau(Vb[(df * 8 + qr) * VP + kb2 * 8 + qc + 4]);
                mma_tf32(o[0][df], af[0][0], af[0][1], af[0][2], af[0][3], b0, b1);
                mma_tf32(o[1][df], af[1][0], af[1][1], af[1][2], af[1][3], b0, b1);
            }
        }
        __syncthreads();
    }

    // epilogue
#pragma unroll
    for (int mf = 0; mf < 2; mf++) {
        const float inv0 = 1.0f / lrow[mf][0], inv1 = 1.0f / lrow[mf][1];
        const int gi = i0 + w * 32 + mf * 16 + qr;
#pragma unroll
        for (int df = 0; df < 8; df++) {
            const int col = n * CH + h * DHEAD + df * 8 + qc * 2;
            out[(size_t)col * LSEQ + gi]           = tf32r(o[mf][df][0] * inv0);
            out[(size_t)(col + 1) * LSEQ + gi]     = tf32r(o[mf][df][1] * inv0);
            out[(size_t)col * LSEQ + gi + 8]       = tf32r(o[mf][df][2] * inv1);
            out[(size_t)(col + 1) * LSEQ + gi + 8] = tf32r(o[mf][df][3] * inv1);
        }
    }
}

// ---------------------------------------------------------------------------
// Launch
// ---------------------------------------------------------------------------
extern "C" void kernel_launch(void* const* d_in, const int* in_sizes, int n_in,
                              void* d_out, int out_size)
{
    const float* x     = (const float*)d_in[0];
    const float* w_qkv = (const float*)d_in[1];
    const float* w_out = (const float*)d_in[2];
    const float* b_out = (const float*)d_in[3];
    float* out = (float*)d_out;

    float *qkv, *att, *xr, *wqT, *woT;
    cudaGetSymbolAddress((void**)&qkv, g_qkv);
    cudaGetSymbolAddress((void**)&att, g_att);
    cudaGetSymbolAddress((void**)&xr,  g_x);
    cudaGetSymbolAddress((void**)&wqT, g_wqkvT);
    cudaGetSymbolAddress((void**)&woT, g_woutT);

    cudaFuncSetAttribute(gemm_cp, cudaFuncAttributeMaxDynamicSharedMemorySize, G_SMEM);
    cudaFuncSetAttribute(flash5,  cudaFuncAttributeMaxDynamicSharedMemorySize, FL_SMEM);

    // prep
    {
        const int n4 = NB * CH * LSEQ / 4;
        round4_kernel<<<(n4 + 255) / 256, 256>>>((const float4*)x, (float4*)xr, n4);
        transpose_round<<<dim3(CH / 32, QKV_CH / 32), dim3(32, 8)>>>(w_qkv, wqT, QKV_CH, CH);
        transpose_round<<<dim3(CH / 32, CH / 32),     dim3(32, 8)>>>(w_out, woT, CH, CH);
    }

    // 1) qkv[n] = w_qkv @ x[n]
    {
        dim3 grid(LSEQ / 128, QKV_CH / 128, NB);
        gemm_cp<<<grid, 128, G_SMEM>>>(wqT, xr, qkv, nullptr,
                                       QKV_CH, LSEQ, CH,
                                       (long)CH * LSEQ, (long)QKV_CH * LSEQ, 1);
    }
    // 2) flash attention -> att[n, (h d), l]
    {
        dim3 grid(LSEQ / 256, NB * NHEADS);
        flash5<<<grid, 256, FL_SMEM>>>(qkv, att);
    }
    // 3) out[n] = w_out @ att[n] + b_out
    {
        dim3 grid(LSEQ / 128, CH / 128, NB);
        gemm_cp<<<grid, 128, G_SMEM>>>(woT, att, out, b_out,
                                       CH, LSEQ, CH,
                                       (long)CH * LSEQ, (long)CH * LSEQ, 0);
    }
}

// round 6
// speedup vs baseline: 1.5186x; 1.5186x over previous
#include <cuda_runtime.h>
#include <cuda_fp16.h>
#include <math.h>
#include <stdint.h>

#define NB     4
#define CH     512
#define LSEQ   2048
#define NHEADS 8
#define DHEAD  64
#define QKV_CH 1536
#define QSCALE 0.18033688f   /* 0.125 * log2(e) */

// ---------------------------------------------------------------------------
// Scratch (no cudaMalloc allowed)
// ---------------------------------------------------------------------------
__device__ __half g_xh  [(size_t)NB * LSEQ * CH];     // x^T   [n][L][C]
__device__ __half g_qkh [(size_t)NB * LSEQ * 1024];   // q,k^T [n][L][1024]
__device__ __half g_vh  [(size_t)NB * CH * LSEQ];     // v     [n][512][L]
__device__ __half g_atth[(size_t)NB * LSEQ * CH];     // att^T [n][L][512]
__device__ __half g_wqkvh[QKV_CH * CH];
__device__ __half g_wouth[CH * CH];

// ---------------------------------------------------------------------------
// helpers
// ---------------------------------------------------------------------------
__device__ __forceinline__ float ex2(float x) {
    float r; asm("ex2.approx.f32 %0, %1;" : "=f"(r) : "f"(x)); return r;
}
__device__ __forceinline__ uint32_t h2pack(float x, float y) {
    __half2 h = __floats2half2_rn(x, y);
    return *(uint32_t*)&h;
}
__device__ __forceinline__ void mma_f16(float c[4],
    uint32_t a0, uint32_t a1, uint32_t a2, uint32_t a3,
    uint32_t b0, uint32_t b1)
{
    asm volatile(
        "mma.sync.aligned.m16n8k16.row.col.f32.f16.f16.f32 "
        "{%0,%1,%2,%3}, {%4,%5,%6,%7}, {%8,%9}, {%0,%1,%2,%3};"
        : "+f"(c[0]), "+f"(c[1]), "+f"(c[2]), "+f"(c[3])
        : "r"(a0), "r"(a1), "r"(a2), "r"(a3), "r"(b0), "r"(b1));
}
__device__ __forceinline__ void ldsm4(uint32_t r[4], uint32_t addr) {
    asm volatile("ldmatrix.sync.aligned.m8n8.x4.shared.b16 {%0,%1,%2,%3}, [%4];"
        : "=r"(r[0]), "=r"(r[1]), "=r"(r[2]), "=r"(r[3]) : "r"(addr));
}
__device__ __forceinline__ void cp128(uint32_t dst, const void* src) {
    asm volatile("cp.async.cg.shared.global [%0], [%1], 16;" :: "r"(dst), "l"(src));
}
#define CP_COMMIT() asm volatile("cp.async.commit_group;")
#define CP_WAIT(N)  asm volatile("cp.async.wait_group %0;" :: "n"(N))

// ---------------------------------------------------------------------------
// prep: float->half convert; x transpose to [L][C] half
// ---------------------------------------------------------------------------
__global__ void conv_half(const float4* __restrict__ in, __half2* __restrict__ out, int n4)
{
    int i = blockIdx.x * blockDim.x + threadIdx.x;
    if (i < n4) {
        float4 v = in[i];
        out[2 * i]     = __floats2half2_rn(v.x, v.y);
        out[2 * i + 1] = __floats2half2_rn(v.z, v.w);
    }
}

// in [R][Cc] float (+z*R*Cc), out [Cc][R] half (+z*R*Cc)
__global__ void transpose_half(const float* __restrict__ in, __half* __restrict__ out,
                               int R, int Cc)
{
    __shared__ float tile[32][33];
    in  += (size_t)blockIdx.z * R * Cc;
    out += (size_t)blockIdx.z * R * Cc;
    const int c0 = blockIdx.x * 32;
    const int r0 = blockIdx.y * 32;
    const int tx = threadIdx.x, ty = threadIdx.y;
#pragma unroll
    for (int r = 0; r < 32; r += 8)
        tile[ty + r][tx] = in[(size_t)(r0 + ty + r) * Cc + c0 + tx];
    __syncthreads();
#pragma unroll
    for (int r = 0; r < 32; r += 8)
        out[(size_t)(c0 + ty + r) * R + r0 + tx] = __float2half(tile[tx][ty + r]);
}

// ---------------------------------------------------------------------------
// fp16 GEMM: C[z][m][n] = A[m][k] @ B[z][n][k]^T. 128x128 block, 4 warps
// (64x64 warp tile), k-step 32, 3-stage cp.async, ldmatrix fragments.
// mode 0: C float [M][N] + bias. mode 1 (QKV): rows<1024 -> qkh transposed
// half [N][1024]; rows>=1024 -> vh half [512][N].
// ---------------------------------------------------------------------------
#define GSW    40
#define GSTG   (128 * GSW)                    // halfs per stage per matrix
#define G_SMEM (2 * 3 * GSTG * 2)             // 61440 bytes

__global__ __launch_bounds__(128, 2)
void gemm_h(const __half* __restrict__ A, const __half* __restrict__ B,
            float* __restrict__ Cf, const float* __restrict__ bias,
            __half* __restrict__ qkh, __half* __restrict__ vh, int mode)
{
    extern __shared__ __half gsm[];
    __half* Asm = gsm;
    __half* Bsm = gsm + 3 * GSTG;

    const int t    = threadIdx.x;
    const int lane = t & 31;
    const int w    = t >> 5;
    const int qr   = lane >> 2;
    const int qc   = lane & 3;
    const int bm   = blockIdx.y * 128;
    const int bn   = blockIdx.x * 128;
    const int z    = blockIdx.z;

    B += (size_t)z * LSEQ * CH;     // [L][512] half

    const int wm = (w >> 1) * 64;
    const int wn = (w & 1) * 64;

    const uint32_t aBase = (uint32_t)__cvta_generic_to_shared(Asm);
    const uint32_t bBase = (uint32_t)__cvta_generic_to_shared(Bsm);

    auto stage = [&](int slab, int buf) {
        const __half* aSrc = A + (size_t)(bm + t) * CH + slab * 32;
        const __half* bSrc = B + (size_t)(bn + t) * CH + slab * 32;
        uint32_t aDst = aBase + (uint32_t)((buf * GSTG + t * GSW) * 2);
        uint32_t bDst = bBase + (uint32_t)((buf * GSTG + t * GSW) * 2);
#pragma unroll
        for (int c = 0; c < 4; c++) {
            cp128(aDst + c * 16, aSrc + c * 8);
            cp128(bDst + c * 16, bSrc + c * 8);
        }
    };

    float acc[4][8][4];
#pragma unroll
    for (int i = 0; i < 4; i++)
#pragma unroll
        for (int j = 0; j < 8; j++)
#pragma unroll
            for (int r = 0; r < 4; r++) acc[i][j][r] = 0.0f;

    stage(0, 0); CP_COMMIT();
    stage(1, 1); CP_COMMIT();

    const int nslabs = CH / 32;     // 16
    for (int i = 0; i < nslabs; i++) {
        const int s = i % 3;
        if (i + 2 < nslabs) { stage(i + 2, (i + 2) % 3); CP_COMMIT(); CP_WAIT(2); }
        else if (i + 1 < nslabs) { CP_WAIT(1); }
        else { CP_WAIT(0); }
        __syncthreads();

        const uint32_t aS = aBase + (uint32_t)(s * GSTG * 2);
        const uint32_t bS = bBase + (uint32_t)(s * GSTG * 2);

#pragma unroll
        for (int kk = 0; kk < 2; kk++) {
            const int kc = kk * 16 + (lane >> 4) * 8;           // A col
            const int bkc = kk * 16 + ((lane >> 3) & 1) * 8;    // B col
            uint32_t af[4][4];
#pragma unroll
            for (int mf = 0; mf < 4; mf++)
                ldsm4(af[mf], aS + (uint32_t)(((wm + mf * 16 + (lane & 15)) * GSW + kc) * 2));
            uint32_t bf[8][2];
#pragma unroll
            for (int np = 0; np < 4; np++) {
                uint32_t r[4];
                const int row = wn + np * 16 + ((lane >> 4) << 3) + (lane & 7);
                ldsm4(r, bS + (uint32_t)((row * GSW + bkc) * 2));
                bf[2 * np][0] = r[0]; bf[2 * np][1] = r[1];
                bf[2 * np + 1][0] = r[2]; bf[2 * np + 1][1] = r[3];
            }
#pragma unroll
            for (int nf = 0; nf < 8; nf++)
#pragma unroll
                for (int mf = 0; mf < 4; mf++)
                    mma_f16(acc[mf][nf], af[mf][0], af[mf][1], af[mf][2], af[mf][3],
                            bf[nf][0], bf[nf][1]);
        }
        __syncthreads();
    }

    if (mode == 0) {
        Cf += (size_t)z * CH * LSEQ;
#pragma unroll
        for (int mf = 0; mf < 4; mf++) {
            const int row = bm + wm + mf * 16 + qr;
            const float bv0 = bias[row], bv1 = bias[row + 8];
#pragma unroll
            for (int nf = 0; nf < 8; nf++) {
                const int col = bn + wn + nf * 8 + qc * 2;
                *(float2*)(Cf + (size_t)row * LSEQ + col) =
                    make_float2(acc[mf][nf][0] + bv0, acc[mf][nf][1] + bv0);
                *(float2*)(Cf + (size_t)(row + 8) * LSEQ + col) =
                    make_float2(acc[mf][nf][2] + bv1, acc[mf][nf][3] + bv1);
            }
        }
    } else if (bm < 1024) {
        // q,k rows: transposed half out [L][1024]
        qkh += (size_t)z * LSEQ * 1024;
#pragma unroll
        for (int mf = 0; mf < 4; mf++) {
            const int row = bm + wm + mf * 16 + qr;
#pragma unroll
            for (int nf = 0; nf < 8; nf++) {
                const int col = bn + wn + nf * 8 + qc * 2;
                qkh[(size_t)col * 1024 + row]           = __float2half(acc[mf][nf][0]);
                qkh[(size_t)(col + 1) * 1024 + row]     = __float2half(acc[mf][nf][1]);
                qkh[(size_t)col * 1024 + row + 8]       = __float2half(acc[mf][nf][2]);
                qkh[(size_t)(col + 1) * 1024 + row + 8] = __float2half(acc[mf][nf][3]);
            }
        }
    } else {
        // v rows: natural half out [512][L]
        vh += (size_t)z * CH * LSEQ;
#pragma unroll
        for (int mf = 0; mf < 4; mf++) {
            const int row = bm - 1024 + wm + mf * 16 + qr;
#pragma unroll
            for (int nf = 0; nf < 8; nf++) {
                const int col = bn + wn + nf * 8 + qc * 2;
                *(uint32_t*)(vh + (size_t)row * LSEQ + col) =
                    h2pack(acc[mf][nf][0], acc[mf][nf][1]);
                *(uint32_t*)(vh + (size_t)(row + 8) * LSEQ + col) =
                    h2pack(acc[mf][nf][2], acc[mf][nf][3]);
            }
        }
    }
}

// ---------------------------------------------------------------------------
// fp16 flash attention: Bq=256, 256 threads, 8 warps x m32n64, Bk=64.
// Q frags in registers (ldmatrix once). K/V double-buffered cp.async.
// P converts C-frag -> A-frag in registers (no shuffles, no smem).
// ---------------------------------------------------------------------------
#define QSW       72
#define QS_HALFS  (256 * QSW)    // 18432
#define KSW       72
#define KS_HALFS  (64 * KSW)     // 4608
#define FL_SMEM   ((QS_HALFS + 4 * KS_HALFS) * 2)   // 73728 bytes

__global__ __launch_bounds__(256, 1)
void flash_h(const __half* __restrict__ qkh, const __half* __restrict__ vh,
             __half* __restrict__ atth)
{
    extern __shared__ __half fsm[];
    const uint32_t qsBase = (uint32_t)__cvta_generic_to_shared(fsm);
    const uint32_t ksBase = qsBase + QS_HALFS * 2;
    const uint32_t vsBase = ksBase + 2 * KS_HALFS * 2;

    const int t    = threadIdx.x;
    const int lane = t & 31;
    const int w    = t >> 5;
    const int qr   = lane >> 2;
    const int qc   = lane & 3;
    const int i0   = blockIdx.x * 256;
    const int nh   = blockIdx.y;
    const int n    = nh >> 3, h = nh & 7;

    qkh  += (size_t)n * LSEQ * 1024;
    vh   += (size_t)n * CH * LSEQ;
    atth += (size_t)n * LSEQ * CH;

    const int sr = t >> 2;       // 0..63
    const int sq = t & 3;

    auto stageKV = [&](int jt, int buf) {
        const __half* ksrc = qkh + (size_t)(jt * 64 + sr) * 1024 + 512 + h * 64;
        const __half* vsrc = vh + (size_t)(h * 64 + sr) * LSEQ + jt * 64;
        uint32_t kdst = ksBase + (uint32_t)((buf * KS_HALFS + sr * KSW) * 2);
        uint32_t vdst = vsBase + (uint32_t)((buf * KS_HALFS + sr * KSW) * 2);
#pragma unroll
        for (int c = 0; c < 2; c++) {
            const int ch = sq + 4 * c;
            cp128(kdst + ch * 16, ksrc + ch * 8);
            cp128(vdst + ch * 16, vsrc + ch * 8);
        }
    };

    stageKV(0, 0); CP_COMMIT();
    // stage Q tile [256][64]
    {
        const __half* qsrc = qkh + (size_t)(i0 + t) * 1024 + h * 64;
        uint32_t qdst = qsBase + (uint32_t)(t * QSW * 2);
#pragma unroll
        for (int c = 0; c < 8; c++)
            cp128(qdst + c * 16, qsrc + c * 8);
    }
    CP_COMMIT();
    CP_WAIT(0);
    __syncthreads();

    // Q fragments into registers, scaled by 0.125*log2e
    uint32_t qf[2][4][4];
    {
        const __half2 qs2 = __floats2half2_rn(QSCALE, QSCALE);
#pragma unroll
        for (int mf = 0; mf < 2; mf++)
#pragma unroll
            for (int kk = 0; kk < 4; kk++) {
                const int row = w * 32 + mf * 16 + (lane & 15);
                const int col = kk * 16 + (lane >> 4) * 8;
                ldsm4(qf[mf][kk], qsBase + (uint32_t)((row * QSW + col) * 2));
#pragma unroll
                for (int r = 0; r < 4; r++) {
                    __half2 v = __hmul2(*(__half2*)&qf[mf][kk][r], qs2);
                    qf[mf][kk][r] = *(uint32_t*)&v;
                }
            }
    }

    float mrow[2][2], lrow[2][2];
    float o[2][8][4];
#pragma unroll
    for (int mf = 0; mf < 2; mf++) {
        mrow[mf][0] = -1e30f; mrow[mf][1] = -1e30f;
        lrow[mf][0] = 0.0f;   lrow[mf][1] = 0.0f;
#pragma unroll
        for (int df = 0; df < 8; df++)
#pragma unroll
            for (int r = 0; r < 4; r++) o[mf][df][r] = 0.0f;
    }

    const int njt = LSEQ / 64;
    for (int jt = 0; jt < njt; jt++) {
        const int s = jt & 1;
        if (jt + 1 < njt) { stageKV(jt + 1, s ^ 1); CP_COMMIT(); CP_WAIT(1); }
        else { CP_WAIT(0); }
        __syncthreads();

        // ---- S = Q K^T ----
        float sreg[2][8][4];
#pragma unroll
        for (int mf = 0; mf < 2; mf++)
#pragma unroll
            for (int nf = 0; nf < 8; nf++)
#pragma unroll
                for (int r = 0; r < 4; r++) sreg[mf][nf][r] = 0.0f;

#pragma unroll
        for (int kk = 0; kk < 4; kk++) {
            const int bcol = kk * 16 + ((lane >> 3) & 1) * 8;
            uint32_t bf[8][2];
#pragma unroll
            for (int np = 0; np < 4; np++) {
                uint32_t r[4];
                const int row = np * 16 + ((lane >> 4) << 3) + (lane & 7);
                ldsm4(r, ksBase + (uint32_t)((s * KS_HALFS + row * KSW + bcol) * 2));
                bf[2 * np][0] = r[0]; bf[2 * np][1] = r[1];
                bf[2 * np + 1][0] = r[2]; bf[2 * np + 1][1] = r[3];
            }
#pragma unroll
            for (int nf = 0; nf < 8; nf++) {
                mma_f16(sreg[0][nf], qf[0][kk][0], qf[0][kk][1], qf[0][kk][2], qf[0][kk][3],
                        bf[nf][0], bf[nf][1]);
                mma_f16(sreg[1][nf], qf[1][kk][0], qf[1][kk][1], qf[1][kk][2], qf[1][kk][3],
                        bf[nf][0], bf[nf][1]);
            }
        }

        // ---- online softmax (base 2) + P -> fp16 A-fragments ----
        uint32_t pf[2][4][4];
#pragma unroll
        for (int mf = 0; mf < 2; mf++) {
            float rm0 = -1e30f, rm1 = -1e30f;
#pragma unroll
            for (int nf = 0; nf < 8; nf++) {
                rm0 = fmaxf(rm0, fmaxf(sreg[mf][nf][0], sreg[mf][nf][1]));
                rm1 = fmaxf(rm1, fmaxf(sreg[mf][nf][2], sreg[mf][nf][3]));
            }
            rm0 = fmaxf(rm0, __shfl_xor_sync(0xffffffffu, rm0, 1));
            rm0 = fmaxf(rm0, __shfl_xor_sync(0xffffffffu, rm0, 2));
            rm1 = fmaxf(rm1, __shfl_xor_sync(0xffffffffu, rm1, 1));
            rm1 = fmaxf(rm1, __shfl_xor_sync(0xffffffffu, rm1, 2));

            const float mn0 = fmaxf(mrow[mf][0], rm0);
            const float mn1 = fmaxf(mrow[mf][1], rm1);
            const float al0 = ex2(mrow[mf][0] - mn0);
            const float al1 = ex2(mrow[mf][1] - mn1);
            mrow[mf][0] = mn0; mrow[mf][1] = mn1;

            float rs0 = 0.0f, rs1 = 0.0f;
#pragma unroll
            for (int nf = 0; nf < 8; nf++) {
                sreg[mf][nf][0] = ex2(sreg[mf][nf][0] - mn0);
                sreg[mf][nf][1] = ex2(sreg[mf][nf][1] - mn0);
                sreg[mf][nf][2] = ex2(sreg[mf][nf][2] - mn1);
                sreg[mf][nf][3] = ex2(sreg[mf][nf][3] - mn1);
                rs0 += sreg[mf][nf][0] + sreg[mf][nf][1];
                rs1 += sreg[mf][nf][2] + sreg[mf][nf][3];
            }
            rs0 += __shfl_xor_sync(0xffffffffu, rs0, 1);
            rs0 += __shfl_xor_sync(0xffffffffu, rs0, 2);
            rs1 += __shfl_xor_sync(0xffffffffu, rs1, 1);
            rs1 += __shfl_xor_sync(0xffffffffu, rs1, 2);

            lrow[mf][0] = lrow[mf][0] * al0 + rs0;
            lrow[mf][1] = lrow[mf][1] * al1 + rs1;

            if (!__all_sync(0xffffffffu, (al0 == 1.0f) && (al1 == 1.0f))) {
#pragma unroll
                for (int df = 0; df < 8; df++) {
                    o[mf][df][0] *= al0; o[mf][df][1] *= al0;
                    o[mf][df][2] *= al1; o[mf][df][3] *= al1;
                }
            }
            // C-frag -> A-frag: direct pack, no shuffles
#pragma unroll
            for (int kk = 0; kk < 4; kk++) {
                pf[mf][kk][0] = h2pack(sreg[mf][2 * kk][0],     sreg[mf][2 * kk][1]);
                pf[mf][kk][1] = h2pack(sreg[mf][2 * kk][2],     sreg[mf][2 * kk][3]);
                pf[mf][kk][2] = h2pack(sreg[mf][2 * kk + 1][0], sreg[mf][2 * kk + 1][1]);
                pf[mf][kk][3] = h2pack(sreg[mf][2 * kk + 1][2], sreg[mf][2 * kk + 1][3]);
            }
        }

        // ---- O += P @ V (V stored [d][j], B-frag n=d, k=j) ----
#pragma unroll
        for (int kk = 0; kk < 4; kk++) {
            const int bcol = kk * 16 + ((lane >> 3) & 1) * 8;
            uint32_t vf[8][2];
#pragma unroll
            for (int dp = 0; dp < 4; dp++) {
                uint32_t r[4];
                const int row = dp * 16 + ((lane >> 4) << 3) + (lane & 7);
                ldsm4(r, vsBase + (uint32_t)((s * KS_HALFS + row * KSW + bcol) * 2));
                vf[2 * dp][0] = r[0]; vf[2 * dp][1] = r[1];
                vf[2 * dp + 1][0] = r[2]; vf[2 * dp + 1][1] = r[3];
            }
#pragma unroll
            for (int df = 0; df < 8; df++) {
                mma_f16(o[0][df], pf[0][kk][0], pf[0][kk][1], pf[0][kk][2], pf[0][kk][3],
                        vf[df][0], vf[df][1]);
                mma_f16(o[1][df], pf[1][kk][0], pf[1][kk][1], pf[1][kk][2], pf[1][kk][3],
                        vf[df][0], vf[df][1]);
            }
        }
        __syncthreads();
    }

    // epilogue: atth[l][h*64+d] = half(O / l)
#pragma unroll
    for (int mf = 0; mf < 2; mf++) {
        const float inv0 = 1.0f / lrow[mf][0], inv1 = 1.0f / lrow[mf][1];
        const int gi = i0 + w * 32 + mf * 16 + qr;
#pragma unroll
        for (int df = 0; df < 8; df++) {
            const int col = h * 64 + df * 8 + qc * 2;
            *(uint32_t*)(atth + (size_t)gi * CH + col) =
                h2pack(o[mf][df][0] * inv0, o[mf][df][1] * inv0);
            *(uint32_t*)(atth + (size_t)(gi + 8) * CH + col) =
                h2pack(o[mf][df][2] * inv1, o[mf][df][3] * inv1);
        }
    }
}

// ---------------------------------------------------------------------------
// Launch
// ---------------------------------------------------------------------------
extern "C" void kernel_launch(void* const* d_in, const int* in_sizes, int n_in,
                              void* d_out, int out_size)
{
    const float* x     = (const float*)d_in[0];
    const float* w_qkv = (const float*)d_in[1];
    const float* w_out = (const float*)d_in[2];
    const float* b_out = (const float*)d_in[3];
    float* out = (float*)d_out;

    __half *xh, *qkh, *vh, *atth, *wqh, *woh;
    cudaGetSymbolAddress((void**)&xh,   g_xh);
    cudaGetSymbolAddress((void**)&qkh,  g_qkh);
    cudaGetSymbolAddress((void**)&vh,   g_vh);
    cudaGetSymbolAddress((void**)&atth, g_atth);
    cudaGetSymbolAddress((void**)&wqh,  g_wqkvh);
    cudaGetSymbolAddress((void**)&woh,  g_wouth);

    cudaFuncSetAttribute(gemm_h,  cudaFuncAttributeMaxDynamicSharedMemorySize, G_SMEM);
    cudaFuncSetAttribute(flash_h, cudaFuncAttributeMaxDynamicSharedMemorySize, FL_SMEM);

    // prep: weights -> half; x -> [L][C] half
    conv_half<<<(QKV_CH * CH / 4 + 255) / 256, 256>>>((const float4*)w_qkv, (__half2*)wqh, QKV_CH * CH / 4);
    conv_half<<<(CH * CH / 4 + 255) / 256, 256>>>((const float4*)w_out, (__half2*)woh, CH * CH / 4);
    transpose_half<<<dim3(LSEQ / 32, CH / 32, NB), dim3(32, 8)>>>(x, xh, CH, LSEQ);

    // 1) QKV projection: q,k transposed to [L][1024], v natural [512][L]
    {
        dim3 grid(LSEQ / 128, QKV_CH / 128, NB);
        gemm_h<<<grid, 128, G_SMEM>>>(wqh, xh, nullptr, nullptr, qkh, vh, 1);
    }
    // 2) flash attention -> atth [L][512] half
    {
        dim3 grid(LSEQ / 256, NB * NHEADS);
        flash_h<<<grid, 256, FL_SMEM>>>(qkh, vh, atth);
    }
    // 3) out = w_out @ att + b_out (float)
    {
        dim3 grid(LSEQ / 128, CH / 128, NB);
        gemm_h<<<grid, 128, G_SMEM>>>(woh, atth, out, b_out, nullptr, nullptr, 0);
    }
}